// round 15
// baseline (speedup 1.0000x reference)
#include <cuda_runtime.h>
#include <cuda_bf16.h>
#include <math.h>
#include <stdint.h>

#define NQ 131072
#define NS 262144
#define D  256
#define C  64
#define MT 128

// ---------------- device scratch ----------------
__device__ int   g_cntp[148 * 64];          // per-kc histograms (h==0 CTAs)
__device__ uint4 g_Pbf4[2048];              // 32KB: prototypes bf16, swizzled+k-permuted, /p_norm
__device__ float g_part[296 * 8192];        // 9.25MB: per-CTA partial [64][128]

extern __shared__ char smem_raw[];

__device__ __forceinline__ uint32_t smem_u32(const void* p) {
    uint32_t a;
    asm("{ .reg .u64 t; cvta.to.shared.u64 t, %1; cvt.u32.u64 %0, t; }" : "=r"(a) : "l"(p));
    return a;
}
__device__ __forceinline__ void ldm4(uint32_t& r0, uint32_t& r1, uint32_t& r2, uint32_t& r3,
                                     uint32_t addr) {
    asm volatile("ldmatrix.sync.aligned.m8n8.x4.shared.b16 {%0,%1,%2,%3}, [%4];"
                 : "=r"(r0), "=r"(r1), "=r"(r2), "=r"(r3) : "r"(addr));
}
__device__ __forceinline__ void ldm4t(uint32_t& r0, uint32_t& r1, uint32_t& r2, uint32_t& r3,
                                      uint32_t addr) {
    asm volatile("ldmatrix.sync.aligned.m8n8.x4.trans.shared.b16 {%0,%1,%2,%3}, [%4];"
                 : "=r"(r0), "=r"(r1), "=r"(r2), "=r"(r3) : "r"(addr));
}
__device__ __forceinline__ void mma16816(float* d, uint32_t a0, uint32_t a1, uint32_t a2,
                                         uint32_t a3, uint32_t b0, uint32_t b1) {
    asm volatile("mma.sync.aligned.m16n8k16.row.col.f32.bf16.bf16.f32 "
                 "{%0,%1,%2,%3}, {%4,%5,%6,%7}, {%8,%9}, {%0,%1,%2,%3};"
                 : "+f"(d[0]), "+f"(d[1]), "+f"(d[2]), "+f"(d[3])
                 : "r"(a0), "r"(a1), "r"(a2), "r"(a3), "r"(b0), "r"(b1));
}

// ---------------- segment sum as GEMM: partial[c][d] = OneHot^T @ S ----------------
// Persistent: 296 CTAs (one exact wave at occ 2). kc = b>>1 in [0,148), h = b&1.
// CTA processes 64-row tiles tg = kc + t*148 (t < ntiles; 28 for kc<100 else 27).
#define NKC      148
#define TROWS    64
#define TOTTILES 4096                       // NS / 64
#define OFF_OH   32768
#define OFF_CNT  49152
#define SEG_SMEM (OFF_CNT + 256)

__global__ void __launch_bounds__(256, 2) k_seg(const float* __restrict__ S,
                                                const int* __restrict__ L) {
    uint32_t sb = smem_u32(smem_raw);
    int* cnts = (int*)(smem_raw + OFF_CNT);
    const int tid = threadIdx.x;
    const int wid = tid >> 5;
    const int lid = tid & 31;
    const int kc  = blockIdx.x >> 1;
    const int h   = blockIdx.x & 1;
    const int ntiles = (kc < TOTTILES - NKC * 27) ? 28 : 27;   // kc<100 -> 28
    const float4* Sp = (const float4*)S;

    if (tid < C) cnts[tid] = 0;
#pragma unroll
    for (int i = 0; i < 4; i++)
        ((uint4*)(smem_raw + OFF_OH))[tid + i * 256] = make_uint4(0, 0, 0, 0);
    __syncthreads();

    float acc[4][2][4];
#pragma unroll
    for (int mt = 0; mt < 4; mt++)
#pragma unroll
        for (int nt = 0; nt < 2; nt++)
#pragma unroll
            for (int j = 0; j < 4; j++) acc[mt][nt][j] = 0.0f;

    float4 pf[8];
    auto ldg_tile = [&](int t) {
        size_t base = (size_t)(kc + t * NKC) * TROWS;
#pragma unroll
        for (int it = 0; it < 8; it++) {
            int f = it * 256 + tid;
            int trow = f >> 5, col4 = f & 31;
            pf[it] = __ldg(Sp + (base + trow) * 64 + h * 32 + col4);
        }
    };
    auto sts_tile = [&](int buf) {
#pragma unroll
        for (int it = 0; it < 8; it++) {
            int f = it * 256 + tid;
            int trow = f >> 5, col4 = f & 31;
            __nv_bfloat162 p0 = __floats2bfloat162_rn(pf[it].x, pf[it].y);
            __nv_bfloat162 p1 = __floats2bfloat162_rn(pf[it].z, pf[it].w);
            uint2 u = { *(uint32_t*)&p0, *(uint32_t*)&p1 };
            uint32_t addr = buf * 16384 + trow * 256 +
                            ((((col4 >> 1) ^ (trow & 7))) << 4) + ((col4 & 1) << 3);
            *(uint2*)(smem_raw + addr) = u;
        }
    };

    const unsigned short one_bf = 0x3F80u;
    uint32_t oldA[2] = { 0xFFFFFFFFu, 0xFFFFFFFFu };
    int labp[2] = { 0, 0 };

    int lab0 = 0;
    if (tid < TROWS) {
        lab0    = __ldg(L + (size_t)kc * TROWS + tid);               // tile 0
        labp[1] = __ldg(L + (size_t)(kc + NKC) * TROWS + tid);       // tile 1
        labp[0] = __ldg(L + (size_t)(kc + 2 * NKC) * TROWS + tid);   // tile 2
    }
    ldg_tile(0);
    if (tid < TROWS) {
        uint32_t addr = OFF_OH + lab0 * 128 + ((((tid >> 3) ^ (lab0 & 7))) << 4) + (tid & 7) * 2;
        *(unsigned short*)(smem_raw + addr) = one_bf;
        oldA[0] = addr;
        if (h == 0) atomicAdd(&cnts[lab0], 1);
    }
    sts_tile(0);
    __syncthreads();

    const int am    = lid >> 3;
    const int mrow0 = (am & 1) * 8 + (lid & 7);
    const int agsel = am >> 1;
    auto mma_tile = [&](int buf) {
        uint32_t ohb = OFF_OH + buf * 8192;
#pragma unroll
        for (int ks = 0; ks < 4; ks++) {
            uint32_t a[4][4];
#pragma unroll
            for (int mt = 0; mt < 4; mt++) {
                int m = mt * 16 + mrow0;
                uint32_t g = ks * 2 + agsel;
                ldm4(a[mt][0], a[mt][1], a[mt][2], a[mt][3],
                     sb + ohb + m * 128 + (((g ^ (m & 7))) << 4));
            }
            uint32_t f0, f1, f2, f3;
            {
                int trow = ks * 16 + (am & 1) * 8 + (lid & 7);
                uint32_t g = 2 * wid + (am >> 1);
                ldm4t(f0, f1, f2, f3,
                      sb + buf * 16384 + trow * 256 + (((g ^ (trow & 7))) << 4));
            }
#pragma unroll
            for (int mt = 0; mt < 4; mt++) {
                mma16816(acc[mt][0], a[mt][0], a[mt][1], a[mt][2], a[mt][3], f0, f1);
                mma16816(acc[mt][1], a[mt][0], a[mt][1], a[mt][2], a[mt][3], f2, f3);
            }
        }
    };

    for (int t = 0; t < ntiles; t++) {
        int b = t & 1;
        if (t + 1 < ntiles) ldg_tile(t + 1);
        mma_tile(b);
        if (t + 1 < ntiles && tid < TROWS) {
            int nb = 1 - b;
            int lab = labp[nb];
            uint32_t addr = OFF_OH + nb * 8192 + lab * 128 +
                            ((((tid >> 3) ^ (lab & 7))) << 4) + (tid & 7) * 2;
            if (oldA[nb] != 0xFFFFFFFFu) *(unsigned short*)(smem_raw + oldA[nb]) = 0;
            *(unsigned short*)(smem_raw + addr) = one_bf;
            oldA[nb] = addr;
            if (h == 0) atomicAdd(&cnts[lab], 1);
            if (t + 3 < ntiles)
                labp[nb] = __ldg(L + (size_t)(kc + (t + 3) * NKC) * TROWS + tid);
        }
        if (t + 1 < ntiles) sts_tile(1 - b);
        __syncthreads();
    }

    float* part = g_part + (size_t)blockIdx.x * 8192;
#pragma unroll
    for (int mt = 0; mt < 4; mt++)
#pragma unroll
        for (int nt = 0; nt < 2; nt++) {
            int r0 = 16 * mt + (lid >> 2);
            int dd = 16 * wid + 8 * nt + 2 * (lid & 3);
            float2 lo2 = { acc[mt][nt][0], acc[mt][nt][1] };
            float2 hi2 = { acc[mt][nt][2], acc[mt][nt][3] };
            __stcs((float2*)(part + r0 * 128 + dd), lo2);
            __stcs((float2*)(part + (r0 + 8) * 128 + dd), hi2);
        }
    if (h == 0 && tid < C) g_cntp[kc * 64 + tid] = cnts[tid];
}

// ---------------- fused finalize: reduce 148 partials, count, normalize, store ----------------
// grid 64 (one CTA per class c), 256 threads (one per dim t).
__global__ void __launch_bounds__(256) k_fin3() {
    __shared__ float red[256];
    __shared__ float cnt_s;
    const int c = blockIdx.x, t = threadIdx.x;
    const int h = t >> 7, dl = t & 127;

    // count for class c: threads 0..147 each hold one kc's histogram entry
    float cv = (t < NKC) ? (float)__ldg(&g_cntp[t * 64 + c]) : 0.0f;
    red[t] = cv;
    __syncthreads();
    for (int st = 128; st > 0; st >>= 1) {
        if (t < st) red[t] += red[t + st];
        __syncthreads();
    }
    if (t == 0) cnt_s = red[0];
    __syncthreads();

    // prototype sum: dim t over all 148 parity-matched partials
    const float* src = g_part + (size_t)h * 8192 + c * 128 + dl;
    float s = 0.0f;
#pragma unroll 4
    for (int kc = 0; kc < NKC; kc++) s += __ldg(src + (size_t)kc * 16384);

    float inv_d = 1.0f / fmaxf(cnt_s, 1.0f);
    float p = s * inv_d;
    __syncthreads();
    red[t] = p * p;
    __syncthreads();
    for (int st = 128; st > 0; st >>= 1) {
        if (t < st) red[t] += red[t + st];
        __syncthreads();
    }
    float inv = 1.0f / fmaxf(sqrtf(red[0]), 1e-8f);
    int tp = (t & 0xF0) | (((t >> 1) & 1) << 3) | (((t >> 2) & 3) << 1) | (t & 1);
    uint32_t byte = (uint32_t)(c * 512 + ((((tp >> 3) ^ (c & 7))) << 4) + (tp & 7) * 2);
    ((__nv_bfloat16*)g_Pbf4)[byte >> 1] = __float2bfloat16_rn(p * inv);
}

// fast exp on the FMA pipe
__device__ __forceinline__ float fexp(float x) {
    float y = x * 1.442695041f;
    float r = y + 12582912.0f;
    int n = __float_as_int(r) - 0x4B400000;
    float f = y - (r - 12582912.0f);
    float p = 1.3333558e-3f;
    p = fmaf(p, f, 9.6181291e-3f);
    p = fmaf(p, f, 5.5504109e-2f);
    p = fmaf(p, f, 2.4022651e-1f);
    p = fmaf(p, f, 6.9314718e-1f);
    p = fmaf(p, f, 1.0f);
    return __int_as_float(__float_as_int(p) + (n << 23));
}

// ---------------- query kernel: R12 winner, verbatim ----------------
#define SMEM_QRY 32768

__global__ void __launch_bounds__(256, 3) k_query(const float* __restrict__ Q,
                                                  float* __restrict__ out) {
    uint32_t sb = smem_u32(smem_raw);
    const int tid = threadIdx.x;
    const int wid = tid >> 5;
    const int lid = tid & 31;
    const int qbase = blockIdx.x * MT;

#pragma unroll
    for (int it = 0; it < 8; it++)
        ((uint4*)smem_raw)[tid + it * 256] = g_Pbf4[tid + it * 256];
    __syncthreads();

    const int rA = wid * 16 + (lid >> 2);
    const float* qA = Q + (size_t)(qbase + rA) * D + 4 * (lid & 3);
    const float* qB = qA + 8 * D;

    const int brow0 = ((lid >> 3) >> 1) * 8 + (lid & 7);
    const int bgsel = (lid >> 3) & 1;

    float dacc[8][4];
#pragma unroll
    for (int nt = 0; nt < 8; nt++)
#pragma unroll
        for (int j = 0; j < 4; j++) dacc[nt][j] = 0.0f;

    float ssq0 = 0.0f, ssq1 = 0.0f;

    float4 bufA[2], bufB[2];
    bufA[0] = __ldg((const float4*)(qA));
    bufB[0] = __ldg((const float4*)(qB));
    bufA[1] = __ldg((const float4*)(qA + 16));
    bufB[1] = __ldg((const float4*)(qB + 16));

#pragma unroll
    for (int s = 0; s < 16; s++) {
        float4 vA = bufA[s & 1];
        float4 vB = bufB[s & 1];
        if (s < 14) {
            bufA[s & 1] = __ldg((const float4*)(qA + (s + 2) * 16));
            bufB[s & 1] = __ldg((const float4*)(qB + (s + 2) * 16));
        }
        ssq0 = fmaf(vA.x, vA.x, ssq0); ssq0 = fmaf(vA.y, vA.y, ssq0);
        ssq0 = fmaf(vA.z, vA.z, ssq0); ssq0 = fmaf(vA.w, vA.w, ssq0);
        ssq1 = fmaf(vB.x, vB.x, ssq1); ssq1 = fmaf(vB.y, vB.y, ssq1);
        ssq1 = fmaf(vB.z, vB.z, ssq1); ssq1 = fmaf(vB.w, vB.w, ssq1);

        __nv_bfloat162 ba0 = __floats2bfloat162_rn(vA.x, vA.y);
        __nv_bfloat162 ba2 = __floats2bfloat162_rn(vA.z, vA.w);
        __nv_bfloat162 ba1 = __floats2bfloat162_rn(vB.x, vB.y);
        __nv_bfloat162 ba3 = __floats2bfloat162_rn(vB.z, vB.w);
        uint32_t a0 = *(uint32_t*)&ba0, a1 = *(uint32_t*)&ba1;
        uint32_t a2 = *(uint32_t*)&ba2, a3 = *(uint32_t*)&ba3;

        uint32_t bfr[16];
#pragma unroll
        for (int pp = 0; pp < 4; pp++) {
            int row = pp * 16 + brow0;
            uint32_t g = 2 * s + bgsel;
            ldm4(bfr[pp * 4], bfr[pp * 4 + 1], bfr[pp * 4 + 2], bfr[pp * 4 + 3],
                 sb + row * 512 + (((g ^ (row & 7))) << 4));
        }
#pragma unroll
        for (int nt = 0; nt < 8; nt++)
            mma16816(dacc[nt], a0, a1, a2, a3, bfr[nt * 2], bfr[nt * 2 + 1]);
    }

    ssq0 += __shfl_xor_sync(0xffffffffu, ssq0, 1);
    ssq0 += __shfl_xor_sync(0xffffffffu, ssq0, 2);
    ssq1 += __shfl_xor_sync(0xffffffffu, ssq1, 1);
    ssq1 += __shfl_xor_sync(0xffffffffu, ssq1, 2);

    float dA[16], dB[16];
#pragma unroll
    for (int nt = 0; nt < 8; nt++) {
        dA[nt * 2] = dacc[nt][0]; dA[nt * 2 + 1] = dacc[nt][1];
        dB[nt * 2] = dacc[nt][2]; dB[nt * 2 + 1] = dacc[nt][3];
    }
    float invA = 1.0f / fmaxf(sqrtf(ssq0), 1e-8f);
    float invB = 1.0f / fmaxf(sqrtf(ssq1), 1e-8f);

    // sims bounded in [-1,1] -> no max-subtraction needed
    float sA = 0.0f, sB = 0.0f;
#pragma unroll
    for (int j = 0; j < 16; j++) {
        dA[j] *= invA; sA += fexp(dA[j]);
        dB[j] *= invB; sB += fexp(dB[j]);
    }
#pragma unroll
    for (int w = 1; w < 4; w <<= 1) {
        sA += __shfl_xor_sync(0xffffffffu, sA, w);
        sB += __shfl_xor_sync(0xffffffffu, sB, w);
    }
    float lseA = logf(sA);
    float lseB = logf(sB);

    float* oA = out + (size_t)(qbase + rA) * C + (lid & 3) * 2;
    float* oB = oA + 8 * C;
#pragma unroll
    for (int nt = 0; nt < 8; nt++) {
        float2 a = { dA[nt * 2] - lseA, dA[nt * 2 + 1] - lseA };
        float2 b = { dB[nt * 2] - lseB, dB[nt * 2 + 1] - lseB };
        *(float2*)(oA + nt * 8) = a;
        *(float2*)(oB + nt * 8) = b;
    }
}

extern "C" void kernel_launch(void* const* d_in, const int* in_sizes, int n_in,
                              void* d_out, int out_size) {
    const float* support = (const float*)d_in[0];
    const int*   labels  = (const int*)d_in[1];
    const float* query   = (const float*)d_in[2];
    float*       out     = (float*)d_out;

    cudaFuncSetAttribute(k_seg,   cudaFuncAttributeMaxDynamicSharedMemorySize, SEG_SMEM);
    cudaFuncSetAttribute(k_query, cudaFuncAttributeMaxDynamicSharedMemorySize, SMEM_QRY);

    k_seg<<<296, 256, SEG_SMEM>>>(support, labels);
    k_fin3<<<C, 256>>>();
    k_query<<<NQ / MT, 256, SMEM_QRY>>>(query, out);
}

// round 16
// speedup vs baseline: 1.0939x; 1.0939x over previous
#include <cuda_runtime.h>
#include <cuda_bf16.h>
#include <math.h>
#include <stdint.h>

#define NQ 131072
#define NS 262144
#define D  256
#define C  64
#define MT 128

// ---------------- device scratch ----------------
__device__ int   g_cntp[148 * 64];          // per-kc histograms (h==0 CTAs)
__device__ uint4 g_Pbf4[2048];              // 32KB: prototypes bf16, swizzled+k-permuted, /p_norm
__device__ float g_part[296 * 8192];        // 9.25MB: per-CTA partial [64][128]

extern __shared__ char smem_raw[];

__device__ __forceinline__ uint32_t smem_u32(const void* p) {
    uint32_t a;
    asm("{ .reg .u64 t; cvta.to.shared.u64 t, %1; cvt.u32.u64 %0, t; }" : "=r"(a) : "l"(p));
    return a;
}
__device__ __forceinline__ void ldm4(uint32_t& r0, uint32_t& r1, uint32_t& r2, uint32_t& r3,
                                     uint32_t addr) {
    asm volatile("ldmatrix.sync.aligned.m8n8.x4.shared.b16 {%0,%1,%2,%3}, [%4];"
                 : "=r"(r0), "=r"(r1), "=r"(r2), "=r"(r3) : "r"(addr));
}
__device__ __forceinline__ void ldm4t(uint32_t& r0, uint32_t& r1, uint32_t& r2, uint32_t& r3,
                                      uint32_t addr) {
    asm volatile("ldmatrix.sync.aligned.m8n8.x4.trans.shared.b16 {%0,%1,%2,%3}, [%4];"
                 : "=r"(r0), "=r"(r1), "=r"(r2), "=r"(r3) : "r"(addr));
}
__device__ __forceinline__ void mma16816(float* d, uint32_t a0, uint32_t a1, uint32_t a2,
                                         uint32_t a3, uint32_t b0, uint32_t b1) {
    asm volatile("mma.sync.aligned.m16n8k16.row.col.f32.bf16.bf16.f32 "
                 "{%0,%1,%2,%3}, {%4,%5,%6,%7}, {%8,%9}, {%0,%1,%2,%3};"
                 : "+f"(d[0]), "+f"(d[1]), "+f"(d[2]), "+f"(d[3])
                 : "r"(a0), "r"(a1), "r"(a2), "r"(a3), "r"(b0), "r"(b1));
}

// ---------------- segment sum as GEMM: partial[c][d] = OneHot^T @ S ----------------
// Persistent: 296 CTAs (one exact wave at occ 2). kc = b>>1 in [0,148), h = b&1.
// CTA processes 64-row tiles tg = kc + t*148 (t < ntiles; 28 for kc<100 else 27).
#define NKC      148
#define TROWS    64
#define TOTTILES 4096                       // NS / 64
#define OFF_OH   32768
#define OFF_CNT  49152
#define SEG_SMEM (OFF_CNT + 256)

__global__ void __launch_bounds__(256, 2) k_seg(const float* __restrict__ S,
                                                const int* __restrict__ L) {
    uint32_t sb = smem_u32(smem_raw);
    int* cnts = (int*)(smem_raw + OFF_CNT);
    const int tid = threadIdx.x;
    const int wid = tid >> 5;
    const int lid = tid & 31;
    const int kc  = blockIdx.x >> 1;
    const int h   = blockIdx.x & 1;
    const int ntiles = (kc < TOTTILES - NKC * 27) ? 28 : 27;   // kc<100 -> 28
    const float4* Sp = (const float4*)S;

    if (tid < C) cnts[tid] = 0;
#pragma unroll
    for (int i = 0; i < 4; i++)
        ((uint4*)(smem_raw + OFF_OH))[tid + i * 256] = make_uint4(0, 0, 0, 0);
    __syncthreads();

    float acc[4][2][4];
#pragma unroll
    for (int mt = 0; mt < 4; mt++)
#pragma unroll
        for (int nt = 0; nt < 2; nt++)
#pragma unroll
            for (int j = 0; j < 4; j++) acc[mt][nt][j] = 0.0f;

    float4 pf[8];
    auto ldg_tile = [&](int t) {
        size_t base = (size_t)(kc + t * NKC) * TROWS;
#pragma unroll
        for (int it = 0; it < 8; it++) {
            int f = it * 256 + tid;
            int trow = f >> 5, col4 = f & 31;
            pf[it] = __ldg(Sp + (base + trow) * 64 + h * 32 + col4);
        }
    };
    auto sts_tile = [&](int buf) {
#pragma unroll
        for (int it = 0; it < 8; it++) {
            int f = it * 256 + tid;
            int trow = f >> 5, col4 = f & 31;
            __nv_bfloat162 p0 = __floats2bfloat162_rn(pf[it].x, pf[it].y);
            __nv_bfloat162 p1 = __floats2bfloat162_rn(pf[it].z, pf[it].w);
            uint2 u = { *(uint32_t*)&p0, *(uint32_t*)&p1 };
            uint32_t addr = buf * 16384 + trow * 256 +
                            ((((col4 >> 1) ^ (trow & 7))) << 4) + ((col4 & 1) << 3);
            *(uint2*)(smem_raw + addr) = u;
        }
    };

    const unsigned short one_bf = 0x3F80u;
    uint32_t oldA[2] = { 0xFFFFFFFFu, 0xFFFFFFFFu };
    int labp[2] = { 0, 0 };

    int lab0 = 0;
    if (tid < TROWS) {
        lab0    = __ldg(L + (size_t)kc * TROWS + tid);               // tile 0
        labp[1] = __ldg(L + (size_t)(kc + NKC) * TROWS + tid);       // tile 1
        labp[0] = __ldg(L + (size_t)(kc + 2 * NKC) * TROWS + tid);   // tile 2
    }
    ldg_tile(0);
    if (tid < TROWS) {
        uint32_t addr = OFF_OH + lab0 * 128 + ((((tid >> 3) ^ (lab0 & 7))) << 4) + (tid & 7) * 2;
        *(unsigned short*)(smem_raw + addr) = one_bf;
        oldA[0] = addr;
        if (h == 0) atomicAdd(&cnts[lab0], 1);
    }
    sts_tile(0);
    __syncthreads();

    const int am    = lid >> 3;
    const int mrow0 = (am & 1) * 8 + (lid & 7);
    const int agsel = am >> 1;
    auto mma_tile = [&](int buf) {
        uint32_t ohb = OFF_OH + buf * 8192;
#pragma unroll
        for (int ks = 0; ks < 4; ks++) {
            uint32_t a[4][4];
#pragma unroll
            for (int mt = 0; mt < 4; mt++) {
                int m = mt * 16 + mrow0;
                uint32_t g = ks * 2 + agsel;
                ldm4(a[mt][0], a[mt][1], a[mt][2], a[mt][3],
                     sb + ohb + m * 128 + (((g ^ (m & 7))) << 4));
            }
            uint32_t f0, f1, f2, f3;
            {
                int trow = ks * 16 + (am & 1) * 8 + (lid & 7);
                uint32_t g = 2 * wid + (am >> 1);
                ldm4t(f0, f1, f2, f3,
                      sb + buf * 16384 + trow * 256 + (((g ^ (trow & 7))) << 4));
            }
#pragma unroll
            for (int mt = 0; mt < 4; mt++) {
                mma16816(acc[mt][0], a[mt][0], a[mt][1], a[mt][2], a[mt][3], f0, f1);
                mma16816(acc[mt][1], a[mt][0], a[mt][1], a[mt][2], a[mt][3], f2, f3);
            }
        }
    };

    for (int t = 0; t < ntiles; t++) {
        int b = t & 1;
        if (t + 1 < ntiles) ldg_tile(t + 1);
        mma_tile(b);
        if (t + 1 < ntiles && tid < TROWS) {
            int nb = 1 - b;
            int lab = labp[nb];
            uint32_t addr = OFF_OH + nb * 8192 + lab * 128 +
                            ((((tid >> 3) ^ (lab & 7))) << 4) + (tid & 7) * 2;
            if (oldA[nb] != 0xFFFFFFFFu) *(unsigned short*)(smem_raw + oldA[nb]) = 0;
            *(unsigned short*)(smem_raw + addr) = one_bf;
            oldA[nb] = addr;
            if (h == 0) atomicAdd(&cnts[lab], 1);
            if (t + 3 < ntiles)
                labp[nb] = __ldg(L + (size_t)(kc + (t + 3) * NKC) * TROWS + tid);
        }
        if (t + 1 < ntiles) sts_tile(1 - b);
        __syncthreads();
    }

    float* part = g_part + (size_t)blockIdx.x * 8192;
#pragma unroll
    for (int mt = 0; mt < 4; mt++)
#pragma unroll
        for (int nt = 0; nt < 2; nt++) {
            int r0 = 16 * mt + (lid >> 2);
            int dd = 16 * wid + 8 * nt + 2 * (lid & 3);
            float2 lo2 = { acc[mt][nt][0], acc[mt][nt][1] };
            float2 hi2 = { acc[mt][nt][2], acc[mt][nt][3] };
            __stcs((float2*)(part + r0 * 128 + dd), lo2);
            __stcs((float2*)(part + (r0 + 8) * 128 + dd), hi2);
        }
    if (h == 0 && tid < C) g_cntp[kc * 64 + tid] = cnts[tid];
}

// ---------------- fused finalize v2: MLP-rich reduce, count, normalize, store ----------------
// grid 64 (one CTA per class c), 256 threads (one per dim t).
// Prototype-sum loads are issued FIRST (4 independent chains, fully unrolled ->
// front-batched LDGs, MLP ~50); the count tree runs while they fly.
__global__ void __launch_bounds__(256) k_fin3() {
    __shared__ float red[256];
    const int c = blockIdx.x, t = threadIdx.x;
    const int h = t >> 7, dl = t & 127;

    // issue all 148 partial loads up front via 4 independent accumulators
    const float* src = g_part + (size_t)h * 8192 + c * 128 + dl;
    float s0 = 0.0f, s1 = 0.0f, s2 = 0.0f, s3 = 0.0f;
#pragma unroll
    for (int kc = 0; kc < 36; kc++) {
        s0 += __ldg(src + (size_t)(kc * 4 + 0) * 16384);
        s1 += __ldg(src + (size_t)(kc * 4 + 1) * 16384);
        s2 += __ldg(src + (size_t)(kc * 4 + 2) * 16384);
        s3 += __ldg(src + (size_t)(kc * 4 + 3) * 16384);
    }
    s0 += __ldg(src + (size_t)144 * 16384);
    s1 += __ldg(src + (size_t)145 * 16384);
    s2 += __ldg(src + (size_t)146 * 16384);
    s3 += __ldg(src + (size_t)147 * 16384);
    float s = (s0 + s1) + (s2 + s3);

    // count for class c (tree over 148 histogram entries)
    red[t] = (t < NKC) ? (float)__ldg(&g_cntp[t * 64 + c]) : 0.0f;
    __syncthreads();
    for (int st = 128; st > 0; st >>= 1) {
        if (t < st) red[t] += red[t + st];
        __syncthreads();
    }
    float cnt = red[0];
    __syncthreads();

    float p = s / fmaxf(cnt, 1.0f);
    red[t] = p * p;
    __syncthreads();
    for (int st = 128; st > 0; st >>= 1) {
        if (t < st) red[t] += red[t + st];
        __syncthreads();
    }
    float inv = 1.0f / fmaxf(sqrtf(red[0]), 1e-8f);
    int tp = (t & 0xF0) | (((t >> 1) & 1) << 3) | (((t >> 2) & 3) << 1) | (t & 1);
    uint32_t byte = (uint32_t)(c * 512 + ((((tp >> 3) ^ (c & 7))) << 4) + (tp & 7) * 2);
    ((__nv_bfloat16*)g_Pbf4)[byte >> 1] = __float2bfloat16_rn(p * inv);
}

// fast exp on the FMA pipe
__device__ __forceinline__ float fexp(float x) {
    float y = x * 1.442695041f;
    float r = y + 12582912.0f;
    int n = __float_as_int(r) - 0x4B400000;
    float f = y - (r - 12582912.0f);
    float p = 1.3333558e-3f;
    p = fmaf(p, f, 9.6181291e-3f);
    p = fmaf(p, f, 5.5504109e-2f);
    p = fmaf(p, f, 2.4022651e-1f);
    p = fmaf(p, f, 6.9314718e-1f);
    p = fmaf(p, f, 1.0f);
    return __int_as_float(__float_as_int(p) + (n << 23));
}

// ---------------- query kernel: R12 winner, verbatim ----------------
#define SMEM_QRY 32768

__global__ void __launch_bounds__(256, 3) k_query(const float* __restrict__ Q,
                                                  float* __restrict__ out) {
    uint32_t sb = smem_u32(smem_raw);
    const int tid = threadIdx.x;
    const int wid = tid >> 5;
    const int lid = tid & 31;
    const int qbase = blockIdx.x * MT;

#pragma unroll
    for (int it = 0; it < 8; it++)
        ((uint4*)smem_raw)[tid + it * 256] = g_Pbf4[tid + it * 256];
    __syncthreads();

    const int rA = wid * 16 + (lid >> 2);
    const float* qA = Q + (size_t)(qbase + rA) * D + 4 * (lid & 3);
    const float* qB = qA + 8 * D;

    const int brow0 = ((lid >> 3) >> 1) * 8 + (lid & 7);
    const int bgsel = (lid >> 3) & 1;

    float dacc[8][4];
#pragma unroll
    for (int nt = 0; nt < 8; nt++)
#pragma unroll
        for (int j = 0; j < 4; j++) dacc[nt][j] = 0.0f;

    float ssq0 = 0.0f, ssq1 = 0.0f;

    float4 bufA[2], bufB[2];
    bufA[0] = __ldg((const float4*)(qA));
    bufB[0] = __ldg((const float4*)(qB));
    bufA[1] = __ldg((const float4*)(qA + 16));
    bufB[1] = __ldg((const float4*)(qB + 16));

#pragma unroll
    for (int s = 0; s < 16; s++) {
        float4 vA = bufA[s & 1];
        float4 vB = bufB[s & 1];
        if (s < 14) {
            bufA[s & 1] = __ldg((const float4*)(qA + (s + 2) * 16));
            bufB[s & 1] = __ldg((const float4*)(qB + (s + 2) * 16));
        }
        ssq0 = fmaf(vA.x, vA.x, ssq0); ssq0 = fmaf(vA.y, vA.y, ssq0);
        ssq0 = fmaf(vA.z, vA.z, ssq0); ssq0 = fmaf(vA.w, vA.w, ssq0);
        ssq1 = fmaf(vB.x, vB.x, ssq1); ssq1 = fmaf(vB.y, vB.y, ssq1);
        ssq1 = fmaf(vB.z, vB.z, ssq1); ssq1 = fmaf(vB.w, vB.w, ssq1);

        __nv_bfloat162 ba0 = __floats2bfloat162_rn(vA.x, vA.y);
        __nv_bfloat162 ba2 = __floats2bfloat162_rn(vA.z, vA.w);
        __nv_bfloat162 ba1 = __floats2bfloat162_rn(vB.x, vB.y);
        __nv_bfloat162 ba3 = __floats2bfloat162_rn(vB.z, vB.w);
        uint32_t a0 = *(uint32_t*)&ba0, a1 = *(uint32_t*)&ba1;
        uint32_t a2 = *(uint32_t*)&ba2, a3 = *(uint32_t*)&ba3;

        uint32_t bfr[16];
#pragma unroll
        for (int pp = 0; pp < 4; pp++) {
            int row = pp * 16 + brow0;
            uint32_t g = 2 * s + bgsel;
            ldm4(bfr[pp * 4], bfr[pp * 4 + 1], bfr[pp * 4 + 2], bfr[pp * 4 + 3],
                 sb + row * 512 + (((g ^ (row & 7))) << 4));
        }
#pragma unroll
        for (int nt = 0; nt < 8; nt++)
            mma16816(dacc[nt], a0, a1, a2, a3, bfr[nt * 2], bfr[nt * 2 + 1]);
    }

    ssq0 += __shfl_xor_sync(0xffffffffu, ssq0, 1);
    ssq0 += __shfl_xor_sync(0xffffffffu, ssq0, 2);
    ssq1 += __shfl_xor_sync(0xffffffffu, ssq1, 1);
    ssq1 += __shfl_xor_sync(0xffffffffu, ssq1, 2);

    float dA[16], dB[16];
#pragma unroll
    for (int nt = 0; nt < 8; nt++) {
        dA[nt * 2] = dacc[nt][0]; dA[nt * 2 + 1] = dacc[nt][1];
        dB[nt * 2] = dacc[nt][2]; dB[nt * 2 + 1] = dacc[nt][3];
    }
    float invA = 1.0f / fmaxf(sqrtf(ssq0), 1e-8f);
    float invB = 1.0f / fmaxf(sqrtf(ssq1), 1e-8f);

    // sims bounded in [-1,1] -> no max-subtraction needed
    float sA = 0.0f, sB = 0.0f;
#pragma unroll
    for (int j = 0; j < 16; j++) {
        dA[j] *= invA; sA += fexp(dA[j]);
        dB[j] *= invB; sB += fexp(dB[j]);
    }
#pragma unroll
    for (int w = 1; w < 4; w <<= 1) {
        sA += __shfl_xor_sync(0xffffffffu, sA, w);
        sB += __shfl_xor_sync(0xffffffffu, sB, w);
    }
    float lseA = logf(sA);
    float lseB = logf(sB);

    float* oA = out + (size_t)(qbase + rA) * C + (lid & 3) * 2;
    float* oB = oA + 8 * C;
#pragma unroll
    for (int nt = 0; nt < 8; nt++) {
        float2 a = { dA[nt * 2] - lseA, dA[nt * 2 + 1] - lseA };
        float2 b = { dB[nt * 2] - lseB, dB[nt * 2 + 1] - lseB };
        *(float2*)(oA + nt * 8) = a;
        *(float2*)(oB + nt * 8) = b;
    }
}

extern "C" void kernel_launch(void* const* d_in, const int* in_sizes, int n_in,
                              void* d_out, int out_size) {
    const float* support = (const float*)d_in[0];
    const int*   labels  = (const int*)d_in[1];
    const float* query   = (const float*)d_in[2];
    float*       out     = (float*)d_out;

    cudaFuncSetAttribute(k_seg,   cudaFuncAttributeMaxDynamicSharedMemorySize, SEG_SMEM);
    cudaFuncSetAttribute(k_query, cudaFuncAttributeMaxDynamicSharedMemorySize, SMEM_QRY);

    k_seg<<<296, 256, SEG_SMEM>>>(support, labels);
    k_fin3<<<C, 256>>>();
    k_query<<<NQ / MT, 256, SMEM_QRY>>>(query, out);
}